// round 12
// baseline (speedup 1.0000x reference)
#include <cuda_runtime.h>
#include <cuda_bf16.h>
#include <mma.h>
#include <cstdint>

// InteractionArch via wmma/HMMA split-GEMM (validated R10 math):
// out[b] = concat(dense[b](128),
//                 triu(k=1) of Gram([dense[b]; sparse[b].reshape(26,128)]))
// B=16384, D=128, F=26, OUTW=479.
//
// hi = rn_bf16(x), lo = rn_bf16(x - hi); G = hi.hi^T + hi.lo^T + lo.hi^T
// (lo.lo ~2^-18 dropped) -> rel_err ~4.5e-6 (R10-validated).
//
// R11 restructure: CTA = 192 threads = 2 samples x 3 warps. The 3 warps of a
// sample SHARE one X tile (32 x [128 hi |128 lo] bf16, LDM=264) and each
// computes ONE 16x16 output tile: (0,0), (0,1), (1,1). smem 71680->33792 B
// per CTA -> 6 CTAs/SM -> 36 warps/SM (vs 12). Balanced: 24 mma + 32 ldsm
// per warp. G reuses the X region after a sync; warp 0 of each sample
// scatters the triu rows.

#define FF   26
#define OUTW 479

#define LDM   264                          // 128 hi + 128 lo + 8 pad (528 B/row)
#define XW_B  (32 * LDM * 2)               // 16896 B per sample region
#define G_LDM 36                           // f32 elems/row of G scratch
#define SM_TOTAL (2 * XW_B)                // 33792 B per CTA

using namespace nvcuda;

__global__ void __launch_bounds__(192, 6)
interact_wmma(const float* __restrict__ dense,
              const float* __restrict__ sparse,
              float* __restrict__ out)
{
    extern __shared__ char smem[];

    const int tid  = threadIdx.x;
    const int wid  = tid >> 5;              // 0..5
    const int lane = tid & 31;
    const int t    = wid / 3;               // sample slot in CTA (0/1)
    const int j    = wid % 3;               // tile role: 0->(0,0) 1->(0,1) 2->(1,1)
    const int s    = blockIdx.x * 2 + t;    // global sample id

    __nv_bfloat16* X  = reinterpret_cast<__nv_bfloat16*>(smem + t * XW_B);
    float*         Gs = reinterpret_cast<float*>(smem + t * XW_B);

    float* ob = out + (size_t)s * OUTW;

    // ---- Stage: warp j loads rows j*9 .. j*9+8 of the 27 (lane = 4-col quad) ----
#pragma unroll
    for (int i = 0; i < 9; ++i) {
        const int r = j * 9 + i;
        const float* src = (r == 0)
            ? dense  + (size_t)s * 128
            : sparse + (size_t)s * (FF * 128) + (size_t)(r - 1) * 128;
        const float4 x = reinterpret_cast<const float4*>(src)[lane];

        if (r == 0) {   // dense passthrough
            ob[lane * 4 + 0] = x.x;
            ob[lane * 4 + 1] = x.y;
            ob[lane * 4 + 2] = x.z;
            ob[lane * 4 + 3] = x.w;
        }

        // hi = rn_bf16(x), packed pairwise (low half = first elem).
        __nv_bfloat162 h01 = __floats2bfloat162_rn(x.x, x.y);
        __nv_bfloat162 h23 = __floats2bfloat162_rn(x.z, x.w);
        const uint32_t hw01 = reinterpret_cast<uint32_t&>(h01);
        const uint32_t hw23 = reinterpret_cast<uint32_t&>(h23);

        // lo = rn_bf16(x - hi); x - hi exact in fp32.
        const float l0 = x.x - __uint_as_float(hw01 << 16);
        const float l1 = x.y - __uint_as_float(hw01 & 0xFFFF0000u);
        const float l2 = x.z - __uint_as_float(hw23 << 16);
        const float l3 = x.w - __uint_as_float(hw23 & 0xFFFF0000u);
        __nv_bfloat162 p01 = __floats2bfloat162_rn(l0, l1);
        __nv_bfloat162 p23 = __floats2bfloat162_rn(l2, l3);

        const uint64_t hi64 = ((uint64_t)hw23 << 32) | hw01;
        const uint64_t lo64 = ((uint64_t)reinterpret_cast<uint32_t&>(p23) << 32)
                              | reinterpret_cast<uint32_t&>(p01);

        *reinterpret_cast<uint64_t*>(X + r * LDM +       4 * lane) = hi64;
        *reinterpret_cast<uint64_t*>(X + r * LDM + 128 + 4 * lane) = lo64;
    }
    // Zero pad rows 27..31 (split across the sample's 3 warps).
    for (int r = 27 + j; r < 32; r += 3)
        reinterpret_cast<uint4*>(X + r * LDM)[lane] = make_uint4(0, 0, 0, 0);

    __syncthreads();

    // ---- One 16x16 tile per warp: (ar,br) = (0,0) / (0,1) / (1,1) ----
    const int ar = (j == 2) ? 1 : 0;
    const int br = (j == 0) ? 0 : 1;
    const __nv_bfloat16* Xa = X + ar * 16 * LDM;
    const __nv_bfloat16* Xb = X + br * 16 * LDM;

    wmma::fragment<wmma::accumulator, 16, 16, 16, float> c;
    wmma::fill_fragment(c, 0.0f);

#pragma unroll
    for (int k = 0; k < 8; ++k) {
        wmma::fragment<wmma::matrix_a, 16, 16, 16, __nv_bfloat16, wmma::row_major> ah, al;
        wmma::fragment<wmma::matrix_b, 16, 16, 16, __nv_bfloat16, wmma::col_major> bh, bl;
        wmma::load_matrix_sync(ah, Xa +       k * 16, LDM);
        wmma::load_matrix_sync(al, Xa + 128 + k * 16, LDM);
        wmma::load_matrix_sync(bh, Xb +       k * 16, LDM);
        wmma::load_matrix_sync(bl, Xb + 128 + k * 16, LDM);
        wmma::mma_sync(c, ah, bh, c);
        wmma::mma_sync(c, ah, bl, c);
        wmma::mma_sync(c, al, bh, c);
    }

    // All reads of X must complete CTA-wide before G overwrites the region.
    __syncthreads();
    wmma::store_matrix_sync(Gs + ar * 16 * G_LDM + br * 16, c, G_LDM,
                            wmma::mem_row_major);
    __syncthreads();

    // ---- Scatter triu: warp j==0 of each sample; lane f emits (f, g) ----
    if (j == 0 && lane < 26) {
        const int f  = lane;
        const int rb = 128 + f * 26 - (f * (f - 1)) / 2 - f - 1;
        for (int g = f + 1; g < 27; ++g)
            ob[rb + g] = Gs[f * G_LDM + g];
    }
}

extern "C" void kernel_launch(void* const* d_in, const int* in_sizes, int n_in,
                              void* d_out, int out_size)
{
    const float* dense  = (const float*)d_in[0];
    const float* sparse = (const float*)d_in[1];
    float* out = (float*)d_out;

    cudaFuncSetAttribute(interact_wmma,
                         cudaFuncAttributeMaxDynamicSharedMemorySize, SM_TOTAL);

    // 16384 samples / 2 per CTA -> 8192 CTAs of 192 threads; 6 CTAs/SM.
    interact_wmma<<<8192, 192, SM_TOTAL>>>(dense, sparse, out);
}

// round 13
// speedup vs baseline: 1.0857x; 1.0857x over previous
#include <cuda_runtime.h>
#include <cuda_bf16.h>
#include <mma.h>
#include <cstdint>

// InteractionArch via wmma/HMMA split-GEMM (R10-validated math):
// out[b] = concat(dense[b](128),
//                 triu(k=1) of Gram([dense[b]; sparse[b].reshape(26,128)]))
// B=16384, D=128, F=26, OUTW=479.
//
// hi = rn_bf16(x), lo = rn_bf16(x - hi); G = hi.hi^T + hi.lo^T + lo.hi^T
// (lo.lo ~2^-18 dropped) -> rel_err 4.5e-6 (R10).
//
// R12: R10 skeleton (one warp = one sample; 3 output tiles per warp so 8
// ldsm serve 9 mma) but K-SPLIT staging: only 64 of the 128 fp32 dims are
// staged at a time (64 hi + 64 lo bf16 cols). Per-warp buffer 17.9->8.7 KB,
// CTA 34.8 KB -> 6 CTAs/SM = 24 warps (was 3 CTAs/12). Accumulators live in
// registers across the two halves; DRAM/ldsm/mma totals unchanged. All
// warp-local (no __syncthreads).

#define FF   26
#define OUTW 479

#define LDM   136                    // 64 hi + 64 lo + 8 pad bf16 (272 B/row)
#define XW_B  (32 * LDM * 2)         // 8704 B per-warp tile
#define G_LDM 36                     // f32 elems/row of G scratch (reuses X)
#define SM_TOTAL (4 * XW_B)          // 34816 B per CTA

using namespace nvcuda;

__global__ void __launch_bounds__(128)
interact_wmma(const float* __restrict__ dense,
              const float* __restrict__ sparse,
              float* __restrict__ out)
{
    extern __shared__ char smem[];

    const int tid  = threadIdx.x;
    const int wid  = tid >> 5;
    const int lane = tid & 31;
    const int s    = blockIdx.x * 4 + wid;      // sample id

    __nv_bfloat16* X  = reinterpret_cast<__nv_bfloat16*>(smem + wid * XW_B);
    float*         Gs = reinterpret_cast<float*>(smem + wid * XW_B);

    float* ob = out + (size_t)s * OUTW;

    const int rh = lane >> 4;        // row within the staged pair (0/1)
    const int q  = lane & 15;        // float4 quad within the 64-dim half

    wmma::fragment<wmma::accumulator, 16, 16, 16, float> c00, c01, c11;
    wmma::fill_fragment(c00, 0.0f);
    wmma::fill_fragment(c01, 0.0f);
    wmma::fill_fragment(c11, 0.0f);

#pragma unroll
    for (int h = 0; h < 2; ++h) {
        // ---- Stage rows 0..27 (row 27 zero), two rows per iteration ----
#pragma unroll
        for (int i = 0; i < 14; ++i) {
            const int r = 2 * i + rh;
            float4 x = make_float4(0.f, 0.f, 0.f, 0.f);
            if (r < 27) {
                const float* src = (r == 0)
                    ? dense  + (size_t)s * 128
                    : sparse + (size_t)s * (FF * 128) + (size_t)(r - 1) * 128;
                x = reinterpret_cast<const float4*>(src + h * 64)[q];
                if (r == 0) {   // dense passthrough for this half's dims
                    float* od = ob + h * 64 + 4 * q;
                    od[0] = x.x; od[1] = x.y; od[2] = x.z; od[3] = x.w;
                }
            }

            // hi = rn_bf16(x), packed pairwise (low half = first elem).
            __nv_bfloat162 h01 = __floats2bfloat162_rn(x.x, x.y);
            __nv_bfloat162 h23 = __floats2bfloat162_rn(x.z, x.w);
            const uint32_t hw01 = reinterpret_cast<uint32_t&>(h01);
            const uint32_t hw23 = reinterpret_cast<uint32_t&>(h23);

            // lo = rn_bf16(x - hi); x - hi exact in fp32.
            const float l0 = x.x - __uint_as_float(hw01 << 16);
            const float l1 = x.y - __uint_as_float(hw01 & 0xFFFF0000u);
            const float l2 = x.z - __uint_as_float(hw23 << 16);
            const float l3 = x.w - __uint_as_float(hw23 & 0xFFFF0000u);
            __nv_bfloat162 p01 = __floats2bfloat162_rn(l0, l1);
            __nv_bfloat162 p23 = __floats2bfloat162_rn(l2, l3);

            const uint64_t hi64 = ((uint64_t)hw23 << 32) | hw01;
            const uint64_t lo64 = ((uint64_t)reinterpret_cast<uint32_t&>(p23) << 32)
                                  | reinterpret_cast<uint32_t&>(p01);

            *reinterpret_cast<uint64_t*>(X + r * LDM +      4 * q) = hi64;
            *reinterpret_cast<uint64_t*>(X + r * LDM + 64 + 4 * q) = lo64;
        }
        // Zero rows 28..31 (cols 0..127 = 256 B/row; 16 lanes x 16 B).
#pragma unroll
        for (int z = 0; z < 2; ++z) {
            const int r = 28 + 2 * z + rh;
            reinterpret_cast<uint4*>(X + r * LDM)[q] = make_uint4(0, 0, 0, 0);
        }
        __syncwarp();

        // ---- 4 k-steps over this half's 64 dims ----
#pragma unroll
        for (int k = 0; k < 4; ++k) {
            wmma::fragment<wmma::matrix_a, 16, 16, 16, __nv_bfloat16, wmma::row_major> a0h, a0l, a1h, a1l;
            wmma::fragment<wmma::matrix_b, 16, 16, 16, __nv_bfloat16, wmma::col_major> b0h, b0l, b1h, b1l;

            wmma::load_matrix_sync(a0h, X +                 k * 16, LDM);
            wmma::load_matrix_sync(a0l, X +            64 + k * 16, LDM);
            wmma::load_matrix_sync(a1h, X + 16 * LDM +      k * 16, LDM);
            wmma::load_matrix_sync(a1l, X + 16 * LDM + 64 + k * 16, LDM);
            wmma::load_matrix_sync(b0h, X +                 k * 16, LDM);
            wmma::load_matrix_sync(b0l, X +            64 + k * 16, LDM);
            wmma::load_matrix_sync(b1h, X + 16 * LDM +      k * 16, LDM);
            wmma::load_matrix_sync(b1l, X + 16 * LDM + 64 + k * 16, LDM);

            wmma::mma_sync(c00, a0h, b0h, c00);
            wmma::mma_sync(c00, a0h, b0l, c00);
            wmma::mma_sync(c00, a0l, b0h, c00);

            wmma::mma_sync(c01, a0h, b1h, c01);
            wmma::mma_sync(c01, a0h, b1l, c01);
            wmma::mma_sync(c01, a0l, b1h, c01);

            wmma::mma_sync(c11, a1h, b1h, c11);
            wmma::mma_sync(c11, a1h, b1l, c11);
            wmma::mma_sync(c11, a1l, b1h, c11);
        }
        __syncwarp();   // half h reads done before half h+1 overwrites X
    }

    // ---- X dead: reuse region as 32x36 f32 G scratch ----
    wmma::store_matrix_sync(Gs,                   c00, G_LDM, wmma::mem_row_major);
    wmma::store_matrix_sync(Gs + 16,              c01, G_LDM, wmma::mem_row_major);
    wmma::store_matrix_sync(Gs + 16 * G_LDM + 16, c11, G_LDM, wmma::mem_row_major);
    __syncwarp();

    // ---- Scatter triu: lane f emits (f, g) for g = f+1..26 ----
    const int f = lane;
    if (f < 26) {
        const int rb = 128 + f * 26 - (f * (f - 1)) / 2 - f - 1;
        for (int g = f + 1; g < 27; ++g)
            ob[rb + g] = Gs[f * G_LDM + g];
    }
}

extern "C" void kernel_launch(void* const* d_in, const int* in_sizes, int n_in,
                              void* d_out, int out_size)
{
    const float* dense  = (const float*)d_in[0];
    const float* sparse = (const float*)d_in[1];
    float* out = (float*)d_out;

    cudaFuncSetAttribute(interact_wmma,
                         cudaFuncAttributeMaxDynamicSharedMemorySize, SM_TOTAL);

    // 16384 samples / 4 per CTA -> 4096 CTAs of 128 threads; 6 CTAs/SM.
    interact_wmma<<<4096, 128, SM_TOTAL>>>(dense, sparse, out);
}